// round 1
// baseline (speedup 1.0000x reference)
#include <cuda_runtime.h>

// MixedActivation: cols with (col % 6) < 3 -> x*x ; else PReLU with slope
// prelu_a[(col % 6) - 3]. x is [1000000, 48] fp32, contiguous.
//
// 48 floats/row = 12 float4/row -> whole tensor is exactly 12M float4s and
// every float4 is row-aligned. For float4 index i, its 4 columns are
// (i % 12)*4 + k, and modulo 6 that phase only depends on r = i % 3:
//   r=0: mods {0,1,2,3}   r=1: mods {4,5,0,1}   r=2: mods {2,3,4,5}
// Computed branchlessly per component.

__global__ void mixed_act_kernel(const float4* __restrict__ in,
                                 const float* __restrict__ pa,
                                 float4* __restrict__ out,
                                 int n4) {
    int i = blockIdx.x * blockDim.x + threadIdx.x;
    if (i >= n4) return;

    const float a0 = __ldg(pa + 0);
    const float a1 = __ldg(pa + 1);
    const float a2 = __ldg(pa + 2);

    float4 v = in[i];

    int r = i % 3;          // phase of this float4 within the 6-col pattern
    int base = r * 4;       // first component's (col % 12); reduce mod 6 per k

    float x[4] = {v.x, v.y, v.z, v.w};
    float o[4];

#pragma unroll
    for (int k = 0; k < 4; k++) {
        int m = base + k;
        if (m >= 6) m -= 6;                       // m = col % 6  (0..5)
        float a = (m == 3) ? a0 : ((m == 4) ? a1 : a2);
        float sq = x[k] * x[k];
        float pr = fmaxf(x[k], 0.0f) + a * fminf(x[k], 0.0f);
        o[k] = (m < 3) ? sq : pr;                 // predicated select, no branch
    }

    out[i] = make_float4(o[0], o[1], o[2], o[3]);
}

extern "C" void kernel_launch(void* const* d_in, const int* in_sizes, int n_in,
                              void* d_out, int out_size) {
    const float* x  = (const float*)d_in[0];
    const float* pa = (const float*)d_in[1];
    float* out = (float*)d_out;

    int n4 = out_size / 4;  // 48M / 4 = 12M float4s (48 divisible by 4)
    int threads = 256;
    int blocks = (n4 + threads - 1) / threads;
    mixed_act_kernel<<<blocks, threads>>>((const float4*)x, pa,
                                          (float4*)out, n4);
}

// round 2
// speedup vs baseline: 1.0312x; 1.0312x over previous
#include <cuda_runtime.h>

// MixedActivation: cols with (col % 6) < 3 -> x*x ; else PReLU with slope
// prelu_a[(col % 6) - 3]. x is [1000000, 48] fp32, contiguous.
//
// 48 floats/row = 12 float4/row. For float4 index i, its phase in the 6-col
// pattern depends only on r = i % 3:
//   r=0: mods {0,1,2,3}   r=1: mods {4,5,0,1}   r=2: mods {2,3,4,5}
//
// R2: 4 float4s per thread (batched loads -> MLP=4 per thread), streaming
// cache hints (__ldcs/__stcs) since nothing is ever re-touched.

#define UNROLL 4
#define TPB 256

__global__ void mixed_act_kernel(const float4* __restrict__ in,
                                 const float* __restrict__ pa,
                                 float4* __restrict__ out,
                                 int n4) {
    const int base = blockIdx.x * (TPB * UNROLL) + threadIdx.x;

    const float a0 = __ldg(pa + 0);
    const float a1 = __ldg(pa + 1);
    const float a2 = __ldg(pa + 2);

    // Batch all loads first: 4 independent LDG.128 outstanding per thread.
    float4 v[UNROLL];
    bool ok[UNROLL];
#pragma unroll
    for (int k = 0; k < UNROLL; k++) {
        int i = base + k * TPB;
        ok[k] = (i < n4);
        if (ok[k]) v[k] = __ldcs(&in[i]);
    }

#pragma unroll
    for (int k = 0; k < UNROLL; k++) {
        int i = base + k * TPB;
        if (!ok[k]) continue;

        int r = i % 3;       // phase of this float4 within the 6-col pattern
        int m0 = r * 4;      // (col % 12) of component 0; reduce mod 6 per c

        float x[4] = {v[k].x, v[k].y, v[k].z, v[k].w};
        float o[4];
#pragma unroll
        for (int c = 0; c < 4; c++) {
            int m = m0 + c;
            if (m >= 6) m -= 6;                   // m = col % 6 (0..5)
            float a = (m == 3) ? a0 : ((m == 4) ? a1 : a2);
            float sq = x[c] * x[c];
            float pr = fmaxf(x[c], 0.0f) + a * fminf(x[c], 0.0f);
            o[c] = (m < 3) ? sq : pr;             // predicated select
        }
        __stcs(&out[i], make_float4(o[0], o[1], o[2], o[3]));
    }
}

extern "C" void kernel_launch(void* const* d_in, const int* in_sizes, int n_in,
                              void* d_out, int out_size) {
    const float* x  = (const float*)d_in[0];
    const float* pa = (const float*)d_in[1];
    float* out = (float*)d_out;

    int n4 = out_size / 4;  // 12M float4s
    int blocks = (n4 + TPB * UNROLL - 1) / (TPB * UNROLL);
    mixed_act_kernel<<<blocks, TPB>>>((const float4*)x, pa, (float4*)out, n4);
}

// round 4
// speedup vs baseline: 1.0317x; 1.0005x over previous
#include <cuda_runtime.h>

// MixedActivation: cols with (col % 6) < 3 -> x*x ; else PReLU with slope
// prelu_a[(col % 6) - 3]. x is [1000000, 48] fp32, contiguous.
//
// 48 floats/row = 12 float4/row. For float4 index i, its phase in the 6-col
// pattern depends only on r = i % 3:
//   r=0: mods {0,1,2,3}   r=1: mods {4,5,0,1}   r=2: mods {2,3,4,5}
//
// R3 resubmit (R3 run died to container infra failure, no measurement):
// 8 float4s per thread, all loads front-batched (MLP=8/thread) with
// streaming hints; trades occupancy for per-warp request depth.

#define UNROLL 8
#define TPB 256

__global__ void __launch_bounds__(TPB)
mixed_act_kernel(const float4* __restrict__ in,
                 const float* __restrict__ pa,
                 float4* __restrict__ out,
                 int n4) {
    const int base = blockIdx.x * (TPB * UNROLL) + threadIdx.x;

    const float a0 = __ldg(pa + 0);
    const float a1 = __ldg(pa + 1);
    const float a2 = __ldg(pa + 2);

    // Front-batch all loads: 8 independent LDG.128 outstanding per thread.
    float4 v[UNROLL];
    bool ok[UNROLL];
#pragma unroll
    for (int k = 0; k < UNROLL; k++) {
        int i = base + k * TPB;
        ok[k] = (i < n4);
        if (ok[k]) v[k] = __ldcs(&in[i]);
    }

#pragma unroll
    for (int k = 0; k < UNROLL; k++) {
        int i = base + k * TPB;
        if (!ok[k]) continue;

        int r = i % 3;       // phase of this float4 within the 6-col pattern
        int m0 = r * 4;      // (col % 12) of component 0; reduce mod 6 per c

        float x[4] = {v[k].x, v[k].y, v[k].z, v[k].w};
        float o[4];
#pragma unroll
        for (int c = 0; c < 4; c++) {
            int m = m0 + c;
            if (m >= 6) m -= 6;                   // m = col % 6 (0..5)
            float a = (m == 3) ? a0 : ((m == 4) ? a1 : a2);
            float sq = x[c] * x[c];
            float pr = fmaxf(x[c], 0.0f) + a * fminf(x[c], 0.0f);
            o[c] = (m < 3) ? sq : pr;             // predicated select
        }
        __stcs(&out[i], make_float4(o[0], o[1], o[2], o[3]));
    }
}

extern "C" void kernel_launch(void* const* d_in, const int* in_sizes, int n_in,
                              void* d_out, int out_size) {
    const float* x  = (const float*)d_in[0];
    const float* pa = (const float*)d_in[1];
    float* out = (float*)d_out;

    int n4 = out_size / 4;  // 12M float4s
    int blocks = (n4 + TPB * UNROLL - 1) / (TPB * UNROLL);
    mixed_act_kernel<<<blocks, TPB>>>((const float4*)x, pa, (float4*)out, n4);
}